// round 4
// baseline (speedup 1.0000x reference)
#include <cuda_runtime.h>
#include <cstdint>

// Chamfer distance, B=4, N=4096, D=3, single fused kernel.
//
// Identity: min_j ||a-b_j||^2 = |a|^2 + min_j (|b_j|^2 - 2 a.b_j)
// Inner loop (per a-point, per packed b-pair): 3x fma.rn.f32x2 + 2x FMNMX.
//
// Grid: 128 blocks = 4 a-chunks x 4 batches x (2 dirs * 4 j-slices), 256 thr.
// Shared holds one 1024-point b-slice as two float4 arrays whose register
// quads are directly the f32x2 operand pairs (no pack MOVs, LDS.128 loads).
// Each block writes its partial min (incl. |a|^2, clamped >= 0) to
// g_part[point][slice] (no atomics, no init). The last block to finish
// (atomic counter, self-resetting) min-combines the 4 slices, sqrts, and
// does a fixed-order block reduction. Fully deterministic.

#define NB 4
#define NP 4096
#define NSLOT (2 * NB * NP) /* 32768 */

__device__ float g_part[NSLOT * 4];  // [point][slice], 512KB
__device__ int g_count;              // zero-initialized; last block resets to 0

__device__ __forceinline__ unsigned long long pack2(float lo, float hi) {
    unsigned long long r;
    asm("mov.b64 %0, {%1, %2};" : "=l"(r) : "f"(lo), "f"(hi));
    return r;
}
__device__ __forceinline__ void unpack2(unsigned long long v, float& lo, float& hi) {
    asm("mov.b64 {%0, %1}, %2;" : "=f"(lo), "=f"(hi) : "l"(v));
}
__device__ __forceinline__ unsigned long long fmafx2(unsigned long long a, unsigned long long b,
                                                     unsigned long long c) {
    unsigned long long r;
    asm("fma.rn.f32x2 %0, %1, %2, %3;" : "=l"(r) : "l"(a), "l"(b), "l"(c));
    return r;
}

__global__ __launch_bounds__(256) void chamfer_fused(const float* __restrict__ pc1,
                                                     const float* __restrict__ pc2,
                                                     float* __restrict__ out) {
    // 1024 b-points per slice as 512 packed pairs:
    // s1[j] = (bx0, bx1, by0, by1), s2[j] = (bz0, bz1, bw0, bw1)  [w = |b|^2]
    __shared__ ulonglong2 s1[512];
    __shared__ ulonglong2 s2[512];
    __shared__ float red[256];
    __shared__ int lastf;

    const int tid = threadIdx.x;
    const int achunk = blockIdx.x;     // 0..3  (1024 a-points)
    const int batch = blockIdx.y;      // 0..3
    const int dir = blockIdx.z >> 2;   // 0: pc1->pc2, 1: pc2->pc1
    const int slice = blockIdx.z & 3;  // 0..3  (1024 b-points)

    const float* Abase = (dir ? pc2 : pc1) + (size_t)batch * NP * 3;
    const float* Bbase = (dir ? pc1 : pc2) + (size_t)batch * NP * 3 + (size_t)slice * 1024 * 3;

    // Fill shared b-slice.
    for (int j = tid; j < 1024; j += 256) {
        float bx = Bbase[j * 3 + 0];
        float by = Bbase[j * 3 + 1];
        float bz = Bbase[j * 3 + 2];
        float bw = bx * bx + by * by + bz * bz;
        int pair = j >> 1, half = j & 1;
        float* p1 = (float*)&s1[pair];
        float* p2 = (float*)&s2[pair];
        p1[half] = bx;
        p1[2 + half] = by;
        p2[half] = bz;
        p2[2 + half] = bw;
    }
    __syncthreads();

    // Each thread owns 4 a-points.
    unsigned long long nax[4], nay[4], naz[4];
    float asq[4], mlo[4], mhi[4];
#pragma unroll
    for (int k = 0; k < 4; ++k) {
        int p = achunk * 1024 + k * 256 + tid;
        float ax = Abase[p * 3 + 0];
        float ay = Abase[p * 3 + 1];
        float az = Abase[p * 3 + 2];
        nax[k] = pack2(-2.0f * ax, -2.0f * ax);
        nay[k] = pack2(-2.0f * ay, -2.0f * ay);
        naz[k] = pack2(-2.0f * az, -2.0f * az);
        asq[k] = ax * ax + ay * ay + az * az;
        mlo[k] = 3.4e38f;
        mhi[k] = 3.4e38f;
    }

#pragma unroll 4
    for (int j = 0; j < 512; ++j) {
        ulonglong2 v1 = s1[j];  // x=(bx0,bx1) y=(by0,by1)
        ulonglong2 v2 = s2[j];  // x=(bz0,bz1) y=(bw0,bw1)
#pragma unroll
        for (int k = 0; k < 4; ++k) {
            unsigned long long t = fmafx2(naz[k], v2.x, v2.y);  // bw - 2az*bz
            t = fmafx2(nay[k], v1.y, t);
            t = fmafx2(nax[k], v1.x, t);
            float lo, hi;
            unpack2(t, lo, hi);
            mlo[k] = fminf(mlo[k], lo);
            mhi[k] = fminf(mhi[k], hi);
        }
    }

    // Write partial mins (with |a|^2 folded back in, clamped at 0).
#pragma unroll
    for (int k = 0; k < 4; ++k) {
        float m = fmaxf(asq[k] + fminf(mlo[k], mhi[k]), 0.0f);
        int p = dir * (NB * NP) + batch * NP + achunk * 1024 + k * 256 + tid;
        g_part[p * 4 + slice] = m;
    }

    // Last-block finalize.
    __threadfence();
    if (tid == 0) {
        int c = atomicAdd(&g_count, 1);
        lastf = (c == 127);
        if (c == 127) g_count = 0;  // self-reset for next graph replay
    }
    __syncthreads();
    if (!lastf) return;

    float s = 0.0f;
    for (int i = tid; i < NSLOT; i += 256) {
        float4 v = *(const float4*)&g_part[i * 4];
        float m = fminf(fminf(v.x, v.y), fminf(v.z, v.w));
        s += sqrtf(m);
    }
    red[tid] = s;
    __syncthreads();
    for (int off = 128; off > 0; off >>= 1) {
        if (tid < off) red[tid] += red[tid + off];
        __syncthreads();
    }
    if (tid == 0) out[0] = red[0] * (1.0f / (float)NSLOT);
}

extern "C" void kernel_launch(void* const* d_in, const int* in_sizes, int n_in,
                              void* d_out, int out_size) {
    const float* pc1 = (const float*)d_in[0];
    const float* pc2 = (const float*)d_in[1];
    chamfer_fused<<<dim3(4, 4, 8), 256>>>(pc1, pc2, (float*)d_out);
}

// round 5
// speedup vs baseline: 2.0372x; 2.0372x over previous
#include <cuda_runtime.h>
#include <cstdint>

// Chamfer distance, B=4, N=4096, D=3, single fused kernel, 512 blocks.
//
// min_j ||a-b_j||^2 = |a|^2 + min_j (|b_j|^2 - 2 a.b_j)
// Inner: 3x fma.rn.f32x2 (+unpack, 2x FMNMX) per 4 a-points x 2 b-points.
//
// Grid: (4 a-chunks, 4 batches, 32 = dir*16 + slice), 256 threads.
// Slice = 256 b-points in shared as packed float4-style quads (LDS.128
// register quads ARE the f32x2 operands). Each block writes per-slice
// partial mins to g_part[point][16] (no atomics, no init needed).
// Tail is hierarchical: per-group (dir,batch,achunk = 32 groups of 16
// slice-blocks) last-finisher reduces its 1024 points (64KB, overlapped
// with other groups' compute), then the globally-last group finisher sums
// 32 partials in fixed order. Counters self-reset (graph-replay safe);
// all reductions fixed-order -> deterministic.

#define NB 4
#define NP 4096
#define NSLOT (2 * NB * NP) /* 32768 */
#define NSLICE 16
#define NGROUP 32

__device__ float g_part[NSLOT * NSLICE];  // [point][slice], 2MB
__device__ float g_gsum[NGROUP];
__device__ int g_cnt[NGROUP];  // zero-init; self-resetting
__device__ int g_done;         // zero-init; self-resetting

__device__ __forceinline__ unsigned long long pack2(float lo, float hi) {
    unsigned long long r;
    asm("mov.b64 %0, {%1, %2};" : "=l"(r) : "f"(lo), "f"(hi));
    return r;
}
__device__ __forceinline__ void unpack2(unsigned long long v, float& lo, float& hi) {
    asm("mov.b64 {%0, %1}, %2;" : "=f"(lo), "=f"(hi) : "l"(v));
}
__device__ __forceinline__ unsigned long long fmafx2(unsigned long long a, unsigned long long b,
                                                     unsigned long long c) {
    unsigned long long r;
    asm("fma.rn.f32x2 %0, %1, %2, %3;" : "=l"(r) : "l"(a), "l"(b), "l"(c));
    return r;
}

__global__ __launch_bounds__(256) void chamfer_fused(const float* __restrict__ pc1,
                                                     const float* __restrict__ pc2,
                                                     float* __restrict__ out) {
    // 256 b-points as 128 packed pairs:
    // s1[j] = (bx0,bx1,by0,by1), s2[j] = (bz0,bz1,bw0,bw1), w = |b|^2
    __shared__ ulonglong2 s1[128];
    __shared__ ulonglong2 s2[128];
    __shared__ float red[256];
    __shared__ int flag;

    const int tid = threadIdx.x;
    const int achunk = blockIdx.x;      // 0..3  (1024 a-points)
    const int batch = blockIdx.y;       // 0..3
    const int dir = blockIdx.z >> 4;    // 0: pc1->pc2, 1: pc2->pc1
    const int slice = blockIdx.z & 15;  // 0..15 (256 b-points)
    const int group = dir * 16 + batch * 4 + achunk;

    const float* Abase = (dir ? pc2 : pc1) + (size_t)batch * NP * 3;
    const float* Bbase = (dir ? pc1 : pc2) + (size_t)batch * NP * 3 + (size_t)slice * 256 * 3;

    // Fill shared b-slice (1 point per thread).
    {
        float bx = Bbase[tid * 3 + 0];
        float by = Bbase[tid * 3 + 1];
        float bz = Bbase[tid * 3 + 2];
        float bw = bx * bx + by * by + bz * bz;
        int pair = tid >> 1, half = tid & 1;
        float* p1 = (float*)&s1[pair];
        float* p2 = (float*)&s2[pair];
        p1[half] = bx;
        p1[2 + half] = by;
        p2[half] = bz;
        p2[2 + half] = bw;
    }
    __syncthreads();

    // Each thread owns 4 a-points.
    unsigned long long nax[4], nay[4], naz[4];
    float asq[4], mlo[4], mhi[4];
#pragma unroll
    for (int k = 0; k < 4; ++k) {
        int p = achunk * 1024 + k * 256 + tid;
        float ax = Abase[p * 3 + 0];
        float ay = Abase[p * 3 + 1];
        float az = Abase[p * 3 + 2];
        nax[k] = pack2(-2.0f * ax, -2.0f * ax);
        nay[k] = pack2(-2.0f * ay, -2.0f * ay);
        naz[k] = pack2(-2.0f * az, -2.0f * az);
        asq[k] = ax * ax + ay * ay + az * az;
        mlo[k] = 3.4e38f;
        mhi[k] = 3.4e38f;
    }

#pragma unroll 4
    for (int j = 0; j < 128; ++j) {
        ulonglong2 v1 = s1[j];  // x=(bx0,bx1) y=(by0,by1)
        ulonglong2 v2 = s2[j];  // x=(bz0,bz1) y=(bw0,bw1)
#pragma unroll
        for (int k = 0; k < 4; ++k) {
            unsigned long long t = fmafx2(naz[k], v2.x, v2.y);  // bw - 2az*bz
            t = fmafx2(nay[k], v1.y, t);
            t = fmafx2(nax[k], v1.x, t);
            float lo, hi;
            unpack2(t, lo, hi);
            mlo[k] = fminf(mlo[k], lo);
            mhi[k] = fminf(mhi[k], hi);
        }
    }

    // Partial mins (|a|^2 folded in, clamped at 0) -> g_part[point][slice].
    const int pbase = dir * (NB * NP) + batch * NP + achunk * 1024;
#pragma unroll
    for (int k = 0; k < 4; ++k) {
        float m = fmaxf(asq[k] + fminf(mlo[k], mhi[k]), 0.0f);
        g_part[(size_t)(pbase + k * 256 + tid) * NSLICE + slice] = m;
    }

    // ---- Group finalize (last of 16 slice-blocks in this group) ----
    __threadfence();
    if (tid == 0) {
        int c = atomicAdd(&g_cnt[group], 1);
        flag = (c == NSLICE - 1);
        if (flag) g_cnt[group] = 0;  // self-reset for graph replay
    }
    __syncthreads();
    if (!flag) return;
    __threadfence();  // acquire: other slice-blocks' g_part writes

    float s = 0.0f;
#pragma unroll
    for (int k = 0; k < 4; ++k) {
        const float* row = &g_part[(size_t)(pbase + k * 256 + tid) * NSLICE];
        float4 v0 = *(const float4*)(row + 0);
        float4 v1 = *(const float4*)(row + 4);
        float4 v2 = *(const float4*)(row + 8);
        float4 v3 = *(const float4*)(row + 12);
        float m = fminf(fminf(fminf(v0.x, v0.y), fminf(v0.z, v0.w)),
                        fminf(fminf(v1.x, v1.y), fminf(v1.z, v1.w)));
        m = fminf(m, fminf(fminf(fminf(v2.x, v2.y), fminf(v2.z, v2.w)),
                           fminf(fminf(v3.x, v3.y), fminf(v3.z, v3.w))));
        s += sqrtf(m);
    }
    red[tid] = s;
    __syncthreads();
#pragma unroll
    for (int off = 128; off > 0; off >>= 1) {
        if (tid < off) red[tid] += red[tid + off];
        __syncthreads();
    }

    // ---- Global finalize (last of 32 groups) ----
    if (tid == 0) {
        g_gsum[group] = red[0];
        __threadfence();
        int c = atomicAdd(&g_done, 1);
        if (c == NGROUP - 1) {
            g_done = 0;  // self-reset
            __threadfence();
            float total = 0.0f;
            for (int g = 0; g < NGROUP; ++g) total += g_gsum[g];
            out[0] = total * (1.0f / (float)NSLOT);
        }
    }
}

extern "C" void kernel_launch(void* const* d_in, const int* in_sizes, int n_in,
                              void* d_out, int out_size) {
    const float* pc1 = (const float*)d_in[0];
    const float* pc2 = (const float*)d_in[1];
    chamfer_fused<<<dim3(4, 4, 32), 256>>>(pc1, pc2, (float*)d_out);
}